// round 2
// baseline (speedup 1.0000x reference)
#include <cuda_runtime.h>
#include <math.h>

// Problem dims
#define B_  256
#define T_  336
#define I_  16
#define H_  512
#define L_  256
#define O_  10
#define G4  2048   // 4*H

// Recurrence kernel config
#define NCTA 64
#define NTHR 256           // 8 warps
#define JPC  8             // h-columns per CTA (H_/NCTA)

// ---------------- device scratch ----------------
__device__ float    d_Wt[G4 * H_];        // sampled Whh, transposed: [gatecol][k]
__device__ float    d_xg[T_ * G4];        // precomputed input projection for b=255
__device__ float    d_hhist[T_ * H_];     // h_t history (also inter-step broadcast buffer)
__device__ float    d_BLWt[H_ * L_];      // sampled BLW, transposed: [h][l]
__device__ float    d_BLb[L_];            // sampled BLb
__device__ float    d_Wih_s[I_ * G4];     // sampled Wih
__device__ float    d_b_s[G4];            // sampled bias
__device__ volatile unsigned d_flags[NCTA];  // per-CTA epoch flags (grid barrier)

__device__ __forceinline__ float softplusf(float v) {
    return (v > 20.0f) ? v : log1pf(expf(v));
}
// fast (MUFU-based) activations: rel err ~4e-7, far inside the 1e-3 budget
__device__ __forceinline__ float fsig(float v) {
    return __fdividef(1.0f, 1.0f + __expf(-v));
}
__device__ __forceinline__ float ftanh(float v) {
    return __fdividef(2.0f, 1.0f + __expf(-2.0f * v)) - 1.0f;
}

// ---- packed f32x2 helpers (FFMA2) ----
typedef unsigned long long u64t;
__device__ __forceinline__ u64t pack2(float x, float y) {
    u64t r; asm("mov.b64 %0, {%1,%2};" : "=l"(r) : "f"(x), "f"(y)); return r;
}
__device__ __forceinline__ float2 unpack2(u64t v) {
    float2 r; asm("mov.b64 {%0,%1}, %2;" : "=f"(r.x), "=f"(r.y) : "l"(v)); return r;
}
__device__ __forceinline__ u64t ffma2(u64t a, u64t b, u64t c) {
    u64t d; asm("fma.rn.f32x2 %0, %1, %2, %3;" : "=l"(d) : "l"(a), "l"(b), "l"(c)); return d;
}

// ---------------- setup: sample w = mu + softplus(rho)*eps and transpose ----------------
__global__ void sample_transpose(const float* __restrict__ mu,
                                 const float* __restrict__ rho,
                                 const float* __restrict__ eps,
                                 float* __restrict__ out, int R, int C) {
    __shared__ float tile[32][33];
    const int c0 = blockIdx.x * 32;
    const int r0 = blockIdx.y * 32;
    const int tx = threadIdx.x, ty = threadIdx.y;
    const int idx = (r0 + ty) * C + (c0 + tx);
    tile[ty][tx] = mu[idx] + softplusf(rho[idx]) * eps[idx];
    __syncthreads();
    out[(c0 + ty) * R + (r0 + tx)] = tile[tx][ty];
}

// ---------------- setup: small samples (b, BLb) + barrier flag reset ----------------
__global__ void setup_small(const float* __restrict__ b_mu,
                            const float* __restrict__ b_rho,
                            const float* __restrict__ eps_b,
                            const float* __restrict__ blb_mu,
                            const float* __restrict__ blb_rho,
                            const float* __restrict__ eps_blb) {
    const int id = blockIdx.x * blockDim.x + threadIdx.x;
    if (id < G4) d_b_s[id] = b_mu[id] + softplusf(b_rho[id]) * eps_b[id];
    const int id2 = id - G4;
    if (id2 >= 0 && id2 < L_) d_BLb[id2] = blb_mu[id2] + softplusf(blb_rho[id2]) * eps_blb[id2];
    const int id3 = id2 - L_;
    if (id3 >= 0 && id3 < NCTA) d_flags[id3] = 0u;
}

// ---------------- setup: sample Wih ----------------
__global__ void sample_wih(const float* __restrict__ wih_mu,
                           const float* __restrict__ wih_rho,
                           const float* __restrict__ eps_wih) {
    const int id = blockIdx.x * blockDim.x + threadIdx.x;
    if (id < I_ * G4)
        d_Wih_s[id] = wih_mu[id] + softplusf(wih_rho[id]) * eps_wih[id];
}

// ---------------- setup: xg[t][g] (parallel over t AND g) ----------------
__global__ void compute_xg(const float* __restrict__ x,
                           const float* __restrict__ drop_x) {
    const int g = blockIdx.x * blockDim.x + threadIdx.x;
    const int t = blockIdx.y;
    const float* xr = x      + ((size_t)255 * T_ + t) * I_;
    const float* dr = drop_x + ((size_t)255 * T_ + t) * I_;
    float acc = d_b_s[g];
#pragma unroll
    for (int i = 0; i < I_; i++)
        acc = fmaf(xr[i] * dr[i], d_Wih_s[i * G4 + g], acc);
    d_xg[t * G4 + g] = acc;
}

// ---------------- recurrence: persistent kernel, batch row 255 only ----------------
__global__ void __launch_bounds__(NTHR, 1) lstm_recurrence() {
    const int warp = threadIdx.x >> 5;
    const int lane = threadIdx.x & 31;
    const int j    = blockIdx.x * JPC + warp;   // owned h-column, 0..511

    // Register-resident packed weights: W[c][kk] = Whh pair (2k, 2k+1), k-pair = kk*32+lane
    u64t W0[8], W1[8], W2[8], W3[8];
    {
        const float2* r0 = (const float2*)(d_Wt + (size_t)(j          ) * H_);
        const float2* r1 = (const float2*)(d_Wt + (size_t)(j +     H_ ) * H_);
        const float2* r2 = (const float2*)(d_Wt + (size_t)(j + 2 * H_ ) * H_);
        const float2* r3 = (const float2*)(d_Wt + (size_t)(j + 3 * H_ ) * H_);
#pragma unroll
        for (int kk = 0; kk < 8; kk++) {
            const int p = kk * 32 + lane;
            float2 w;
            w = r0[p]; W0[kk] = pack2(w.x, w.y);
            w = r1[p]; W1[kk] = pack2(w.x, w.y);
            w = r2[p]; W2[kk] = pack2(w.x, w.y);
            w = r3[p]; W3[kk] = pack2(w.x, w.y);
        }
    }

    float cstate = 0.0f;   // valid in lane 0 only
    // prefetch xg for t=0 (lanes 0..3 carry the 4 gate preactivations for column j)
    float myxg = (lane < 4) ? __ldg(&d_xg[j + lane * H_]) : 0.0f;

#pragma unroll 1
    for (int t = 0; t < T_; t++) {
        float s0, s1, s2, s3;
        if (t == 0) {
            s0 = s1 = s2 = s3 = 0.0f;
        } else {
            const float2* hp = (const float2*)(d_hhist + (size_t)(t - 1) * H_);
            u64t h[8];
#pragma unroll
            for (int kk = 0; kk < 8; kk++) {
                float2 hv = __ldcg(hp + kk * 32 + lane);
                h[kk] = pack2(hv.x, hv.y);
            }
            u64t a0 = 0ull, a1 = 0ull, a2 = 0ull, a3 = 0ull;
#pragma unroll
            for (int kk = 0; kk < 8; kk++) {
                a0 = ffma2(W0[kk], h[kk], a0);
                a1 = ffma2(W1[kk], h[kk], a1);
                a2 = ffma2(W2[kk], h[kk], a2);
                a3 = ffma2(W3[kk], h[kk], a3);
            }
            float2 f0 = unpack2(a0), f1 = unpack2(a1), f2 = unpack2(a2), f3 = unpack2(a3);
            s0 = f0.x + f0.y; s1 = f1.x + f1.y; s2 = f2.x + f2.y; s3 = f3.x + f3.y;
#pragma unroll
            for (int off = 16; off > 0; off >>= 1) {
                s0 += __shfl_xor_sync(0xffffffffu, s0, off);
                s1 += __shfl_xor_sync(0xffffffffu, s1, off);
                s2 += __shfl_xor_sync(0xffffffffu, s2, off);
                s3 += __shfl_xor_sync(0xffffffffu, s3, off);
            }
        }

        // per-lane gating: lane0=i(sig), lane1=f(sig), lane2=g(tanh), lane3=o(sig)
        float pre = (lane == 0) ? s0 : (lane == 1) ? s1 : (lane == 2) ? s2 : s3;
        pre += myxg;
        float act = (lane == 2) ? ftanh(pre) : fsig(pre);
        const float fv = __shfl_sync(0xffffffffu, act, 1);
        const float gv = __shfl_sync(0xffffffffu, act, 2);
        const float ov = __shfl_sync(0xffffffffu, act, 3);
        if (lane == 0) {
            cstate = fv * cstate + act * gv;
            d_hhist[(size_t)t * H_ + j] = ov * ftanh(cstate);
        }

        // prefetch next step's xg before the barrier (independent of h)
        if (t + 1 < T_)
            myxg = (lane < 4) ? __ldg(&d_xg[(t + 1) * G4 + j + lane * H_]) : 0.0f;

        // ---- distributed-flag grid barrier (monotonic epochs, no atomic contention) ----
        __syncthreads();                      // all warps' h stores issued
        const unsigned target = (unsigned)(t + 1);
        if (warp == 0) {
            if (lane == 0) {
                __threadfence();              // release h stores (cumulative via bar.sync)
                d_flags[blockIdx.x] = target; // own word: no serialization
            }
            unsigned va, vb;
            do {
                va = d_flags[lane];
                vb = d_flags[32 + lane];
            } while (__any_sync(0xffffffffu, (va < target) | (vb < target)));
            __threadfence();                  // acquire
        }
        __syncthreads();
    }
}

// ---------------- epilogue ----------------
#define BPB 4
__global__ void epilogue(const float* __restrict__ drop_h,
                         const float* __restrict__ drop_l,
                         const float* __restrict__ lin_w,
                         float* __restrict__ out) {
    __shared__ float hv[BPB][H_];
    __shared__ float ys[BPB][L_];
    const int bp0 = blockIdx.x * BPB;
    const int tid = threadIdx.x;

    for (int e = tid; e < BPB * H_; e += blockDim.x) {
        const int bb = e / H_, h = e % H_;
        const int bp = bp0 + bb;
        hv[bb][h] = d_hhist[(size_t)(80 + bp) * H_ + h] * drop_h[(size_t)bp * H_ + h];
    }
    __syncthreads();

    const int l = tid;   // 256 threads == L_
    float a0 = d_BLb[l], a1 = a0, a2 = a0, a3 = a0;
    for (int h = 0; h < H_; h++) {
        const float w = d_BLWt[h * L_ + l];
        a0 = fmaf(hv[0][h], w, a0);
        a1 = fmaf(hv[1][h], w, a1);
        a2 = fmaf(hv[2][h], w, a2);
        a3 = fmaf(hv[3][h], w, a3);
    }
    ys[0][l] = fmaxf(a0, 0.f) * drop_l[(size_t)(bp0 + 0) * L_ + l];
    ys[1][l] = fmaxf(a1, 0.f) * drop_l[(size_t)(bp0 + 1) * L_ + l];
    ys[2][l] = fmaxf(a2, 0.f) * drop_l[(size_t)(bp0 + 2) * L_ + l];
    ys[3][l] = fmaxf(a3, 0.f) * drop_l[(size_t)(bp0 + 3) * L_ + l];
    __syncthreads();

    if (tid < 32) {
        for (int bb = 0; bb < BPB; bb++) {
            for (int o = 0; o < O_; o++) {
                float a = 0.f;
                for (int ll = tid; ll < L_; ll += 32)
                    a = fmaf(ys[bb][ll], lin_w[o * L_ + ll], a);
#pragma unroll
                for (int off = 16; off > 0; off >>= 1)
                    a += __shfl_xor_sync(0xffffffffu, a, off);
                if (tid == 0) out[(size_t)(bp0 + bb) * O_ + o] = a;
            }
        }
    }
}

// ---------------- launcher ----------------
extern "C" void kernel_launch(void* const* d_in, const int* in_sizes, int n_in,
                              void* d_out, int out_size) {
    const float* x        = (const float*)d_in[0];
    const float* drop_x   = (const float*)d_in[1];
    const float* drop_h   = (const float*)d_in[2];
    const float* drop_l   = (const float*)d_in[3];
    const float* wih_mu   = (const float*)d_in[4];
    const float* wih_rho  = (const float*)d_in[5];
    const float* eps_wih  = (const float*)d_in[6];
    const float* whh_mu   = (const float*)d_in[7];
    const float* whh_rho  = (const float*)d_in[8];
    const float* eps_whh  = (const float*)d_in[9];
    const float* b_mu     = (const float*)d_in[10];
    const float* b_rho    = (const float*)d_in[11];
    const float* eps_b    = (const float*)d_in[12];
    const float* blw_mu   = (const float*)d_in[13];
    const float* blw_rho  = (const float*)d_in[14];
    const float* eps_blw  = (const float*)d_in[15];
    const float* blb_mu   = (const float*)d_in[16];
    const float* blb_rho  = (const float*)d_in[17];
    const float* eps_blb  = (const float*)d_in[18];
    const float* lin_w    = (const float*)d_in[19];
    float* out = (float*)d_out;

    float* wt_ptr   = nullptr;
    float* blwt_ptr = nullptr;
    cudaGetSymbolAddress((void**)&wt_ptr,   d_Wt);
    cudaGetSymbolAddress((void**)&blwt_ptr, d_BLWt);

    // setup
    setup_small<<<(G4 + L_ + NCTA + 255) / 256, 256>>>(b_mu, b_rho, eps_b,
                                                       blb_mu, blb_rho, eps_blb);
    sample_wih<<<(I_ * G4 + 255) / 256, 256>>>(wih_mu, wih_rho, eps_wih);
    sample_transpose<<<dim3(G4 / 32, H_ / 32), dim3(32, 32)>>>(whh_mu, whh_rho, eps_whh, wt_ptr, H_, G4);
    sample_transpose<<<dim3(H_ / 32, L_ / 32), dim3(32, 32)>>>(blw_mu, blw_rho, eps_blw, blwt_ptr, L_, H_);
    compute_xg<<<dim3(G4 / 256, T_), 256>>>(x, drop_x);

    // recurrence (batch row 255 only — reshape-based "last" slice)
    lstm_recurrence<<<NCTA, NTHR>>>();

    // epilogue
    epilogue<<<L_ / BPB, 256>>>(drop_h, drop_l, lin_w, out);
}

// round 3
// speedup vs baseline: 1.3302x; 1.3302x over previous
#include <cuda_runtime.h>
#include <math.h>

// Problem dims
#define B_  256
#define T_  336
#define I_  16
#define H_  512
#define L_  256
#define O_  10
#define G4  2048   // 4*H

// Recurrence kernel config
#define NCTA 64
#define NTHR 256           // 8 warps
#define JPC  8             // h-columns per CTA (H_/NCTA)
#define FPAD 8             // flag padding: one 32B sector per CTA flag

// ---------------- device scratch ----------------
__device__ float    d_Wt[G4 * H_];        // sampled Whh, transposed: [gatecol][k]
__device__ float    d_xg[T_ * G4];        // precomputed input projection for b=255
__device__ float    d_hhist[T_ * H_];     // h_t history (also inter-step broadcast buffer)
__device__ float    d_BLWt[H_ * L_];      // sampled BLW, transposed: [h][l]
__device__ float    d_BLb[L_];            // sampled BLb
__device__ float    d_Wih_s[I_ * G4];     // sampled Wih
__device__ float    d_b_s[G4];            // sampled bias
__device__ volatile unsigned d_flags[NCTA * FPAD];  // sector-padded per-CTA epoch flags

__device__ __forceinline__ float softplusf(float v) {
    return (v > 20.0f) ? v : log1pf(expf(v));
}
// fast (MUFU-based) activations: rel err ~5e-7, far inside the 1e-3 budget
__device__ __forceinline__ float fsig(float v) {
    return __fdividef(1.0f, 1.0f + __expf(-v));
}
__device__ __forceinline__ float ftanh(float v) {
    return __fdividef(2.0f, 1.0f + __expf(-2.0f * v)) - 1.0f;
}

// ---------------- setup: sample w = mu + softplus(rho)*eps and transpose ----------------
__global__ void sample_transpose(const float* __restrict__ mu,
                                 const float* __restrict__ rho,
                                 const float* __restrict__ eps,
                                 float* __restrict__ out, int R, int C) {
    __shared__ float tile[32][33];
    const int c0 = blockIdx.x * 32;
    const int r0 = blockIdx.y * 32;
    const int tx = threadIdx.x, ty = threadIdx.y;
    const int idx = (r0 + ty) * C + (c0 + tx);
    tile[ty][tx] = mu[idx] + softplusf(rho[idx]) * eps[idx];
    __syncthreads();
    out[(c0 + ty) * R + (r0 + tx)] = tile[tx][ty];
}

// ---------------- setup: small samples (b, BLb) + barrier flag reset ----------------
__global__ void setup_small(const float* __restrict__ b_mu,
                            const float* __restrict__ b_rho,
                            const float* __restrict__ eps_b,
                            const float* __restrict__ blb_mu,
                            const float* __restrict__ blb_rho,
                            const float* __restrict__ eps_blb) {
    const int id = blockIdx.x * blockDim.x + threadIdx.x;
    if (id < G4) d_b_s[id] = b_mu[id] + softplusf(b_rho[id]) * eps_b[id];
    const int id2 = id - G4;
    if (id2 >= 0 && id2 < L_) d_BLb[id2] = blb_mu[id2] + softplusf(blb_rho[id2]) * eps_blb[id2];
    const int id3 = id2 - L_;
    if (id3 >= 0 && id3 < NCTA * FPAD) d_flags[id3] = 0u;
}

// ---------------- setup: sample Wih ----------------
__global__ void sample_wih(const float* __restrict__ wih_mu,
                           const float* __restrict__ wih_rho,
                           const float* __restrict__ eps_wih) {
    const int id = blockIdx.x * blockDim.x + threadIdx.x;
    if (id < I_ * G4)
        d_Wih_s[id] = wih_mu[id] + softplusf(wih_rho[id]) * eps_wih[id];
}

// ---------------- setup: xg[t][g] (parallel over t AND g) ----------------
__global__ void compute_xg(const float* __restrict__ x,
                           const float* __restrict__ drop_x) {
    const int g = blockIdx.x * blockDim.x + threadIdx.x;
    const int t = blockIdx.y;
    const float* xr = x      + ((size_t)255 * T_ + t) * I_;
    const float* dr = drop_x + ((size_t)255 * T_ + t) * I_;
    float acc = d_b_s[g];
#pragma unroll
    for (int i = 0; i < I_; i++)
        acc = fmaf(xr[i] * dr[i], d_Wih_s[i * G4 + g], acc);
    d_xg[t * G4 + g] = acc;
}

// ---------------- recurrence: persistent kernel, batch row 255 only ----------------
__global__ void __launch_bounds__(NTHR, 1) lstm_recurrence() {
    const int warp = threadIdx.x >> 5;
    const int lane = threadIdx.x & 31;
    const int j    = blockIdx.x * JPC + warp;   // owned h-column, 0..511

    // Register-resident weights: W[c][kk] = Whh[k = kk*32+lane][col = j + c*512]
    float W0[16], W1[16], W2[16], W3[16];
#pragma unroll
    for (int kk = 0; kk < 16; kk++) {
        const int k = kk * 32 + lane;
        W0[kk] = d_Wt[(size_t)(j          ) * H_ + k];
        W1[kk] = d_Wt[(size_t)(j +     H_ ) * H_ + k];
        W2[kk] = d_Wt[(size_t)(j + 2 * H_ ) * H_ + k];
        W3[kk] = d_Wt[(size_t)(j + 3 * H_ ) * H_ + k];
    }

    float cstate = 0.0f;   // valid in lane 0 only
    // prefetch xg for t=0 (lanes 0..3 carry the 4 gate preactivations for column j)
    float myxg = (lane < 4) ? __ldg(&d_xg[j + lane * H_]) : 0.0f;

#pragma unroll 1
    for (int t = 0; t < T_; t++) {
        float s0, s1, s2, s3;
        if (t == 0) {
            s0 = s1 = s2 = s3 = 0.0f;
        } else {
            const float* hprev = d_hhist + (size_t)(t - 1) * H_;
            float hreg[16];
#pragma unroll
            for (int kk = 0; kk < 16; kk++)
                hreg[kk] = __ldcg(hprev + kk * 32 + lane);

            float a0 = 0.f, a1 = 0.f, a2 = 0.f, a3 = 0.f;
#pragma unroll
            for (int kk = 0; kk < 16; kk++) {
                const float hv = hreg[kk];
                a0 = fmaf(W0[kk], hv, a0);
                a1 = fmaf(W1[kk], hv, a1);
                a2 = fmaf(W2[kk], hv, a2);
                a3 = fmaf(W3[kk], hv, a3);
            }
            s0 = a0; s1 = a1; s2 = a2; s3 = a3;
#pragma unroll
            for (int off = 16; off > 0; off >>= 1) {
                s0 += __shfl_xor_sync(0xffffffffu, s0, off);
                s1 += __shfl_xor_sync(0xffffffffu, s1, off);
                s2 += __shfl_xor_sync(0xffffffffu, s2, off);
                s3 += __shfl_xor_sync(0xffffffffu, s3, off);
            }
        }

        // per-lane gating: lane0=i(sig), lane1=f(sig), lane2=g(tanh), lane3=o(sig)
        float pre = (lane == 0) ? s0 : (lane == 1) ? s1 : (lane == 2) ? s2 : s3;
        pre += myxg;
        float act = (lane == 2) ? ftanh(pre) : fsig(pre);
        const float fv = __shfl_sync(0xffffffffu, act, 1);
        const float gv = __shfl_sync(0xffffffffu, act, 2);
        const float ov = __shfl_sync(0xffffffffu, act, 3);
        if (lane == 0) {
            cstate = fv * cstate + act * gv;
            d_hhist[(size_t)t * H_ + j] = ov * ftanh(cstate);
        }

        // prefetch next step's xg before the barrier (independent of h)
        if (t + 1 < T_)
            myxg = (lane < 4) ? __ldg(&d_xg[(t + 1) * G4 + j + lane * H_]) : 0.0f;

        // ---- sector-padded distributed-flag grid barrier (monotonic epochs) ----
        __syncthreads();                      // all warps' h stores issued
        const unsigned target = (unsigned)(t + 1);
        if (warp == 0) {
            if (lane == 0) {
                __threadfence();              // release h stores
                d_flags[blockIdx.x * FPAD] = target;   // own 32B sector: no line ping-pong
            }
            unsigned va, vb;
            do {
                va = d_flags[lane * FPAD];
                vb = d_flags[(32 + lane) * FPAD];
            } while (__any_sync(0xffffffffu, (va < target) | (vb < target)));
            __threadfence();                  // acquire
        }
        __syncthreads();
    }
}

// ---------------- epilogue ----------------
#define BPB 4
__global__ void epilogue(const float* __restrict__ drop_h,
                         const float* __restrict__ drop_l,
                         const float* __restrict__ lin_w,
                         float* __restrict__ out) {
    __shared__ float hv[BPB][H_];
    __shared__ float ys[BPB][L_];
    const int bp0 = blockIdx.x * BPB;
    const int tid = threadIdx.x;

    for (int e = tid; e < BPB * H_; e += blockDim.x) {
        const int bb = e / H_, h = e % H_;
        const int bp = bp0 + bb;
        hv[bb][h] = d_hhist[(size_t)(80 + bp) * H_ + h] * drop_h[(size_t)bp * H_ + h];
    }
    __syncthreads();

    const int l = tid;   // 256 threads == L_
    float a0 = d_BLb[l], a1 = a0, a2 = a0, a3 = a0;
    for (int h = 0; h < H_; h++) {
        const float w = d_BLWt[h * L_ + l];
        a0 = fmaf(hv[0][h], w, a0);
        a1 = fmaf(hv[1][h], w, a1);
        a2 = fmaf(hv[2][h], w, a2);
        a3 = fmaf(hv[3][h], w, a3);
    }
    ys[0][l] = fmaxf(a0, 0.f) * drop_l[(size_t)(bp0 + 0) * L_ + l];
    ys[1][l] = fmaxf(a1, 0.f) * drop_l[(size_t)(bp0 + 1) * L_ + l];
    ys[2][l] = fmaxf(a2, 0.f) * drop_l[(size_t)(bp0 + 2) * L_ + l];
    ys[3][l] = fmaxf(a3, 0.f) * drop_l[(size_t)(bp0 + 3) * L_ + l];
    __syncthreads();

    if (tid < 32) {
        for (int bb = 0; bb < BPB; bb++) {
            for (int o = 0; o < O_; o++) {
                float a = 0.f;
                for (int ll = tid; ll < L_; ll += 32)
                    a = fmaf(ys[bb][ll], lin_w[o * L_ + ll], a);
#pragma unroll
                for (int off = 16; off > 0; off >>= 1)
                    a += __shfl_xor_sync(0xffffffffu, a, off);
                if (tid == 0) out[(size_t)(bp0 + bb) * O_ + o] = a;
            }
        }
    }
}

// ---------------- launcher ----------------
extern "C" void kernel_launch(void* const* d_in, const int* in_sizes, int n_in,
                              void* d_out, int out_size) {
    const float* x        = (const float*)d_in[0];
    const float* drop_x   = (const float*)d_in[1];
    const float* drop_h   = (const float*)d_in[2];
    const float* drop_l   = (const float*)d_in[3];
    const float* wih_mu   = (const float*)d_in[4];
    const float* wih_rho  = (const float*)d_in[5];
    const float* eps_wih  = (const float*)d_in[6];
    const float* whh_mu   = (const float*)d_in[7];
    const float* whh_rho  = (const float*)d_in[8];
    const float* eps_whh  = (const float*)d_in[9];
    const float* b_mu     = (const float*)d_in[10];
    const float* b_rho    = (const float*)d_in[11];
    const float* eps_b    = (const float*)d_in[12];
    const float* blw_mu   = (const float*)d_in[13];
    const float* blw_rho  = (const float*)d_in[14];
    const float* eps_blw  = (const float*)d_in[15];
    const float* blb_mu   = (const float*)d_in[16];
    const float* blb_rho  = (const float*)d_in[17];
    const float* eps_blb  = (const float*)d_in[18];
    const float* lin_w    = (const float*)d_in[19];
    float* out = (float*)d_out;

    float* wt_ptr   = nullptr;
    float* blwt_ptr = nullptr;
    cudaGetSymbolAddress((void**)&wt_ptr,   d_Wt);
    cudaGetSymbolAddress((void**)&blwt_ptr, d_BLWt);

    // setup
    setup_small<<<(G4 + L_ + NCTA * FPAD + 255) / 256, 256>>>(b_mu, b_rho, eps_b,
                                                              blb_mu, blb_rho, eps_blb);
    sample_wih<<<(I_ * G4 + 255) / 256, 256>>>(wih_mu, wih_rho, eps_wih);
    sample_transpose<<<dim3(G4 / 32, H_ / 32), dim3(32, 32)>>>(whh_mu, whh_rho, eps_whh, wt_ptr, H_, G4);
    sample_transpose<<<dim3(H_ / 32, L_ / 32), dim3(32, 32)>>>(blw_mu, blw_rho, eps_blw, blwt_ptr, L_, H_);
    compute_xg<<<dim3(G4 / 256, T_), 256>>>(x, drop_x);

    // recurrence (batch row 255 only — reshape-based "last" slice)
    lstm_recurrence<<<NCTA, NTHR>>>();

    // epilogue
    epilogue<<<L_ / BPB, 256>>>(drop_h, drop_l, lin_w, out);
}

// round 4
// speedup vs baseline: 1.6857x; 1.2673x over previous
#include <cuda_runtime.h>
#include <math.h>

// Problem dims
#define B_  256
#define T_  336
#define I_  16
#define H_  512
#define L_  256
#define O_  10
#define G4  2048   // 4*H

// Recurrence kernel config
#define NCTA 64
#define NTHR 256           // 8 warps
#define JPC  8             // h-columns per CTA (H_/NCTA)

// ---------------- device scratch ----------------
__device__ float    d_Wt[G4 * H_];        // sampled Whh, transposed: [gatecol][k]
__device__ float    d_xg[T_ * G4];        // precomputed input projection for b=255
__device__ float    d_hhist[T_ * H_];     // h_t history (also inter-step broadcast buffer)
__device__ float    d_BLWt[H_ * L_];      // sampled BLW, transposed: [h][l]
__device__ float    d_BLb[L_];            // sampled BLb
__device__ float    d_Wih_s[I_ * G4];     // sampled Wih
__device__ float    d_b_s[G4];            // sampled bias

// two-address sense barrier: counter (write-hot) and go-flag (read-mostly)
// on separate 128B lines so arrivals never invalidate the polled line.
__device__ __align__(128) unsigned d_count;
__device__ unsigned _pad_barrier[31];
__device__ __align__(128) volatile unsigned d_go;

__device__ __forceinline__ float softplusf(float v) {
    return (v > 20.0f) ? v : log1pf(expf(v));
}
// fast (MUFU-based) activations: rel err ~5e-7, far inside the 1e-3 budget
__device__ __forceinline__ float fsig(float v) {
    return __fdividef(1.0f, 1.0f + __expf(-v));
}
__device__ __forceinline__ float ftanh(float v) {
    return __fdividef(2.0f, 1.0f + __expf(-2.0f * v)) - 1.0f;
}

// ---------------- setup: sample w = mu + softplus(rho)*eps and transpose ----------------
__global__ void sample_transpose(const float* __restrict__ mu,
                                 const float* __restrict__ rho,
                                 const float* __restrict__ eps,
                                 float* __restrict__ out, int R, int C) {
    __shared__ float tile[32][33];
    const int c0 = blockIdx.x * 32;
    const int r0 = blockIdx.y * 32;
    const int tx = threadIdx.x, ty = threadIdx.y;
    const int idx = (r0 + ty) * C + (c0 + tx);
    tile[ty][tx] = mu[idx] + softplusf(rho[idx]) * eps[idx];
    __syncthreads();
    out[(c0 + ty) * R + (r0 + tx)] = tile[tx][ty];
}

// ---------------- setup: small samples (b, BLb) + barrier reset ----------------
__global__ void setup_small(const float* __restrict__ b_mu,
                            const float* __restrict__ b_rho,
                            const float* __restrict__ eps_b,
                            const float* __restrict__ blb_mu,
                            const float* __restrict__ blb_rho,
                            const float* __restrict__ eps_blb) {
    const int id = blockIdx.x * blockDim.x + threadIdx.x;
    if (id < G4) d_b_s[id] = b_mu[id] + softplusf(b_rho[id]) * eps_b[id];
    const int id2 = id - G4;
    if (id2 >= 0 && id2 < L_) d_BLb[id2] = blb_mu[id2] + softplusf(blb_rho[id2]) * eps_blb[id2];
    if (id == 0) { d_count = 0u; d_go = 0u; }
}

// ---------------- setup: sample Wih ----------------
__global__ void sample_wih(const float* __restrict__ wih_mu,
                           const float* __restrict__ wih_rho,
                           const float* __restrict__ eps_wih) {
    const int id = blockIdx.x * blockDim.x + threadIdx.x;
    if (id < I_ * G4)
        d_Wih_s[id] = wih_mu[id] + softplusf(wih_rho[id]) * eps_wih[id];
}

// ---------------- setup: xg[t][g] (parallel over t AND g) ----------------
__global__ void compute_xg(const float* __restrict__ x,
                           const float* __restrict__ drop_x) {
    const int g = blockIdx.x * blockDim.x + threadIdx.x;
    const int t = blockIdx.y;
    const float* xr = x      + ((size_t)255 * T_ + t) * I_;
    const float* dr = drop_x + ((size_t)255 * T_ + t) * I_;
    float acc = d_b_s[g];
#pragma unroll
    for (int i = 0; i < I_; i++)
        acc = fmaf(xr[i] * dr[i], d_Wih_s[i * G4 + g], acc);
    d_xg[t * G4 + g] = acc;
}

// ---------------- recurrence: persistent kernel, batch row 255 only ----------------
__global__ void __launch_bounds__(NTHR, 1) lstm_recurrence() {
    const int warp = threadIdx.x >> 5;
    const int lane = threadIdx.x & 31;
    const int j    = blockIdx.x * JPC + warp;   // owned h-column, 0..511

    // Register-resident weights: W[c][kk] = Whh[k = kk*32+lane][col = j + c*512]
    float W0[16], W1[16], W2[16], W3[16];
#pragma unroll
    for (int kk = 0; kk < 16; kk++) {
        const int k = kk * 32 + lane;
        W0[kk] = d_Wt[(size_t)(j          ) * H_ + k];
        W1[kk] = d_Wt[(size_t)(j +     H_ ) * H_ + k];
        W2[kk] = d_Wt[(size_t)(j + 2 * H_ ) * H_ + k];
        W3[kk] = d_Wt[(size_t)(j + 3 * H_ ) * H_ + k];
    }

    float cstate = 0.0f;   // valid in lane 0 only
    // prefetch xg for t=0 (lanes 0..3 carry the 4 gate preactivations for column j)
    float myxg = (lane < 4) ? __ldg(&d_xg[j + lane * H_]) : 0.0f;

#pragma unroll 1
    for (int t = 0; t < T_; t++) {
        float s0, s1, s2, s3;
        if (t == 0) {
            s0 = s1 = s2 = s3 = 0.0f;
        } else {
            const float* hprev = d_hhist + (size_t)(t - 1) * H_;
            float hreg[16];
#pragma unroll
            for (int kk = 0; kk < 16; kk++)
                hreg[kk] = __ldcg(hprev + kk * 32 + lane);

            float a0 = 0.f, a1 = 0.f, a2 = 0.f, a3 = 0.f;
#pragma unroll
            for (int kk = 0; kk < 16; kk++) {
                const float hv = hreg[kk];
                a0 = fmaf(W0[kk], hv, a0);
                a1 = fmaf(W1[kk], hv, a1);
                a2 = fmaf(W2[kk], hv, a2);
                a3 = fmaf(W3[kk], hv, a3);
            }
            s0 = a0; s1 = a1; s2 = a2; s3 = a3;
#pragma unroll
            for (int off = 16; off > 0; off >>= 1) {
                s0 += __shfl_xor_sync(0xffffffffu, s0, off);
                s1 += __shfl_xor_sync(0xffffffffu, s1, off);
                s2 += __shfl_xor_sync(0xffffffffu, s2, off);
                s3 += __shfl_xor_sync(0xffffffffu, s3, off);
            }
        }

        // per-lane gating: lane0=i(sig), lane1=f(sig), lane2=g(tanh), lane3=o(sig)
        float pre = (lane == 0) ? s0 : (lane == 1) ? s1 : (lane == 2) ? s2 : s3;
        pre += myxg;
        float act = (lane == 2) ? ftanh(pre) : fsig(pre);
        const float fv = __shfl_sync(0xffffffffu, act, 1);
        const float gv = __shfl_sync(0xffffffffu, act, 2);
        const float ov = __shfl_sync(0xffffffffu, act, 3);
        if (lane == 0) {
            cstate = fv * cstate + act * gv;
            d_hhist[(size_t)t * H_ + j] = ov * ftanh(cstate);
        }

        // prefetch next step's xg before the barrier (independent of h)
        if (t + 1 < T_)
            myxg = (lane < 4) ? __ldg(&d_xg[(t + 1) * G4 + j + lane * H_]) : 0.0f;

        // ---- two-address sense barrier (monotonic epochs) ----
        const unsigned epoch = (unsigned)(t + 1);
        __syncthreads();                       // all warps' h stores issued
        if (warp == 0) {
            if (lane == 0) {
                __threadfence();               // release h stores to L2
                // arrival on the counter line; last arriver publishes the epoch
                unsigned old = atomicAdd(&d_count, 1u);
                if (old == (unsigned)NCTA * epoch - 1u)
                    d_go = epoch;              // separate read-mostly line
            }
            while (d_go < epoch) { }           // broadcast L2 read, 1 write/step
            __threadfence();                   // acquire
        }
        __syncthreads();
    }
}

// ---------------- epilogue ----------------
#define BPB 4
__global__ void epilogue(const float* __restrict__ drop_h,
                         const float* __restrict__ drop_l,
                         const float* __restrict__ lin_w,
                         float* __restrict__ out) {
    __shared__ float hv[BPB][H_];
    __shared__ float ys[BPB][L_];
    const int bp0 = blockIdx.x * BPB;
    const int tid = threadIdx.x;

    for (int e = tid; e < BPB * H_; e += blockDim.x) {
        const int bb = e / H_, h = e % H_;
        const int bp = bp0 + bb;
        hv[bb][h] = d_hhist[(size_t)(80 + bp) * H_ + h] * drop_h[(size_t)bp * H_ + h];
    }
    __syncthreads();

    const int l = tid;   // 256 threads == L_
    float a0 = d_BLb[l], a1 = a0, a2 = a0, a3 = a0;
    for (int h = 0; h < H_; h++) {
        const float w = d_BLWt[h * L_ + l];
        a0 = fmaf(hv[0][h], w, a0);
        a1 = fmaf(hv[1][h], w, a1);
        a2 = fmaf(hv[2][h], w, a2);
        a3 = fmaf(hv[3][h], w, a3);
    }
    ys[0][l] = fmaxf(a0, 0.f) * drop_l[(size_t)(bp0 + 0) * L_ + l];
    ys[1][l] = fmaxf(a1, 0.f) * drop_l[(size_t)(bp0 + 1) * L_ + l];
    ys[2][l] = fmaxf(a2, 0.f) * drop_l[(size_t)(bp0 + 2) * L_ + l];
    ys[3][l] = fmaxf(a3, 0.f) * drop_l[(size_t)(bp0 + 3) * L_ + l];
    __syncthreads();

    if (tid < 32) {
        for (int bb = 0; bb < BPB; bb++) {
            for (int o = 0; o < O_; o++) {
                float a = 0.f;
                for (int ll = tid; ll < L_; ll += 32)
                    a = fmaf(ys[bb][ll], lin_w[o * L_ + ll], a);
#pragma unroll
                for (int off = 16; off > 0; off >>= 1)
                    a += __shfl_xor_sync(0xffffffffu, a, off);
                if (tid == 0) out[(size_t)(bp0 + bb) * O_ + o] = a;
            }
        }
    }
}

// ---------------- launcher ----------------
extern "C" void kernel_launch(void* const* d_in, const int* in_sizes, int n_in,
                              void* d_out, int out_size) {
    const float* x        = (const float*)d_in[0];
    const float* drop_x   = (const float*)d_in[1];
    const float* drop_h   = (const float*)d_in[2];
    const float* drop_l   = (const float*)d_in[3];
    const float* wih_mu   = (const float*)d_in[4];
    const float* wih_rho  = (const float*)d_in[5];
    const float* eps_wih  = (const float*)d_in[6];
    const float* whh_mu   = (const float*)d_in[7];
    const float* whh_rho  = (const float*)d_in[8];
    const float* eps_whh  = (const float*)d_in[9];
    const float* b_mu     = (const float*)d_in[10];
    const float* b_rho    = (const float*)d_in[11];
    const float* eps_b    = (const float*)d_in[12];
    const float* blw_mu   = (const float*)d_in[13];
    const float* blw_rho  = (const float*)d_in[14];
    const float* eps_blw  = (const float*)d_in[15];
    const float* blb_mu   = (const float*)d_in[16];
    const float* blb_rho  = (const float*)d_in[17];
    const float* eps_blb  = (const float*)d_in[18];
    const float* lin_w    = (const float*)d_in[19];
    float* out = (float*)d_out;

    float* wt_ptr   = nullptr;
    float* blwt_ptr = nullptr;
    cudaGetSymbolAddress((void**)&wt_ptr,   d_Wt);
    cudaGetSymbolAddress((void**)&blwt_ptr, d_BLWt);

    // setup
    setup_small<<<(G4 + L_ + 255) / 256, 256>>>(b_mu, b_rho, eps_b,
                                                blb_mu, blb_rho, eps_blb);
    sample_wih<<<(I_ * G4 + 255) / 256, 256>>>(wih_mu, wih_rho, eps_wih);
    sample_transpose<<<dim3(G4 / 32, H_ / 32), dim3(32, 32)>>>(whh_mu, whh_rho, eps_whh, wt_ptr, H_, G4);
    sample_transpose<<<dim3(H_ / 32, L_ / 32), dim3(32, 32)>>>(blw_mu, blw_rho, eps_blw, blwt_ptr, L_, H_);
    compute_xg<<<dim3(G4 / 256, T_), 256>>>(x, drop_x);

    // recurrence (batch row 255 only — reshape-based "last" slice)
    lstm_recurrence<<<NCTA, NTHR>>>();

    // epilogue
    epilogue<<<L_ / BPB, 256>>>(drop_h, drop_l, lin_w, out);
}